// round 9
// baseline (speedup 1.0000x reference)
#include <cuda_runtime.h>

#define BATCH  16
#define H      1024
#define HW     (H*H)
#define NSTRIP 2
#define NCHUNK 9
#define CHUNK  114            // 9*114 = 1026 >= 1024 (last chunk 112 rows)
#define NBLK   (BATCH*NSTRIP*NCHUNK)  // 288
#define NT     160
#define NWARP  5
#define RW     160            // float4 words per smem row (136 used + slack)
#define RING   32
#define F4TOT  ((RING + 6) * RW)

__device__ float        g_accum[BATCH * 5];
__device__ unsigned int g_count;

__device__ __forceinline__ float4 f4z() { return make_float4(0.f, 0.f, 0.f, 0.f); }

__device__ __forceinline__ void epi(float x, float m, float S3, float S15, float S31,
                                    float& a0, float& a1, float& a2, float& a3, float& a4)
{
    float w = 1.f + 5.f * ( fabsf(S3  * (1.f / 9.f)   - m)
                          + fabsf(S15 * (1.f / 225.f) - m)
                          + fabsf(S31 * (1.f / 961.f) - m) );
    float e   = __expf(-fabsf(x));
    float l   = __logf(1.f + e);
    float bce = fmaxf(x, 0.f) - x * m + l;
    float inv = __fdividef(1.f, 1.f + e);
    float sg  = (x >= 0.f) ? inv : e * inv;
    a0 += w;
    a1 += w * bce;
    a2 += sg * m * w;
    a3 += (sg + m) * w;
    a4 += fabsf(sg - m);
}

__global__ __launch_bounds__(NT, 2) void adaptive_loss_main(
    const float* __restrict__ pred, const float* __restrict__ mask, float* __restrict__ out)
{
    extern __shared__ float4 sm4[];
    float4* ringB = sm4;                       // [RING][RW]
    float4* sUB   = sm4 + RING * RW;           // [2 parities][3 arrays][RW]
    float*  smf   = (float*)sm4;
    float*  swsum = (float*)(sm4 + F4TOT);     // 2*8
    float*  sred  = swsum + 16;                // NWARP*5
    unsigned int* sflag = (unsigned int*)(sred + NWARP * 5);

    const int tid  = threadIdx.x;
    const int lane = tid & 31;
    const int warp = tid >> 5;

    const int bid = blockIdx.x;
    const int b   = bid / (NSTRIP * NCHUNK);
    const int r2  = bid % (NSTRIP * NCHUNK);
    const int s   = r2 / NCHUNK;
    const int c   = r2 % NCHUNK;
    const int y0  = c * CHUNK;
    const int rows = (H - y0 < CHUNK) ? (H - y0) : CHUNK;

    // thread's global f4 word within a row: strip s covers words s*128-4 .. s*128+155
    const int  gw  = s * 128 - 4 + tid;
    const bool wok = ((unsigned)gw < 256u);        // in-image word
    const bool cwv = (tid >= 4 && tid < 132);      // words that produce output (data cols)

    const float4* mb4 = (const float4*)(mask + (size_t)b * HW);
    const float4* pb4 = (const float4*)(pred + (size_t)b * HW);

    float4 U31 = f4z(), U15 = f4z(), U3 = f4z();
    float a0 = 0.f, a1 = 0.f, a2 = 0.f, a3 = 0.f, a4 = 0.f;
    int par = 0;

    // ================= priming: rows y0-16 .. y0+14 (j = 0..30) =================
    float4 mA, mB;
    {
        int r0 = y0 - 16, r1 = y0 - 15;
        mA = (r0 >= 0 && wok) ? mb4[(size_t)r0 * 256 + gw] : f4z();
        mB = (r1 >= 0 && wok) ? mb4[(size_t)r1 * 256 + gw] : f4z();
    }
    int sp = (y0 - 16 + 544) & 31;                 // slot of row being written
    #pragma unroll 1
    for (int j = 0; j < 31; ++j) {
        int rn = y0 - 14 + j;
        float4 mC = (rn >= 0 && rn < H && wok) ? mb4[(size_t)rn * 256 + gw] : f4z();

        float4 v = mA; v.y += v.x; v.z += v.y; v.w += v.z;
        float tot = v.w;
        #pragma unroll
        for (int d = 1; d < 32; d <<= 1) {
            float t = __shfl_up_sync(0xffffffffu, tot, d);
            if (lane >= d) tot += t;
        }
        if (lane == 31) swsum[par * 8 + warp] = tot;
        __syncthreads();
        float wv = (lane < NWARP) ? swsum[par * 8 + lane] : 0.f;
        #pragma unroll
        for (int d = 1; d < 8; d <<= 1) {
            float t = __shfl_up_sync(0xffffffffu, wv, d);
            if (lane >= d) wv += t;
        }
        float off = __shfl_sync(0xffffffffu, wv, (warp > 0) ? (warp - 1) : 0);
        if (warp == 0) off = 0.f;
        float bse = off + (tot - v.w);
        float4 P = make_float4(v.x + bse, v.y + bse, v.z + bse, v.w + bse);
        ringB[sp * RW + tid] = P;

        U31.x += P.x; U31.y += P.y; U31.z += P.z; U31.w += P.w;
        if (j >= 8 && j <= 22) { U15.x += P.x; U15.y += P.y; U15.z += P.z; U15.w += P.w; }
        if (j >= 14 && j <= 16) { U3.x += P.x; U3.y += P.y; U3.z += P.z; U3.w += P.w; }

        mA = mB; mB = mC;
        sp = (sp + 1) & 31;
        par ^= 1;
    }
    // mA = raw mask row y0+15, mB = y0+16; sp = slot(y0+15); U centered at y0-1

    float4 pO = f4z();
    float4 pA2 = cwv ? pb4[(size_t)y0 * 256 + gw] : f4z();
    float4 pB2 = cwv ? pb4[(size_t)(y0 + 1) * 256 + gw] : f4z();

    // ================= main: rows y0 .. y0+rows-1; consume row y-1 =================
    #pragma unroll 1
    for (int i = 0; i < rows; ++i) {
        const int y  = y0 + i;
        const int rm = y + 17, rp = y + 2;
        float4 mC = (rm < H && wok) ? mb4[(size_t)rm * 256 + gw] : f4z();
        float4 pC = (rp < H && cwv) ? pb4[(size_t)rp * 256 + gw] : f4z();

        // scan raw mask row y+15
        float4 v = mA; v.y += v.x; v.z += v.y; v.w += v.z;
        float tot = v.w;
        #pragma unroll
        for (int d = 1; d < 32; d <<= 1) {
            float t = __shfl_up_sync(0xffffffffu, tot, d);
            if (lane >= d) tot += t;
        }
        if (lane == 31) swsum[par * 8 + warp] = tot;
        __syncthreads();                               // the ONLY barrier per row
        float wv = (lane < NWARP) ? swsum[par * 8 + lane] : 0.f;
        #pragma unroll
        for (int d = 1; d < 8; d <<= 1) {
            float t = __shfl_up_sync(0xffffffffu, wv, d);
            if (lane >= d) wv += t;
        }
        float off = __shfl_sync(0xffffffffu, wv, (warp > 0) ? (warp - 1) : 0);
        if (warp == 0) off = 0.f;
        float bse = off + (tot - v.w);
        float4 P = make_float4(v.x + bse, v.y + bse, v.z + bse, v.w + bse);

        // vertical running sums (own word only)
        float4 r16 = ringB[((sp + 1)  & 31) * RW + tid];   // P(y-16)
        float4 r7  = ringB[((sp + 24) & 31) * RW + tid];   // P(y+7)
        float4 r8  = ringB[((sp + 9)  & 31) * RW + tid];   // P(y-8)
        float4 r1  = ringB[((sp + 18) & 31) * RW + tid];   // P(y+1)
        float4 rm2 = ringB[((sp + 15) & 31) * RW + tid];   // P(y-2)
        ringB[sp * RW + tid] = P;                          // P(y+15)

        U31.x += P.x - r16.x;  U31.y += P.y - r16.y;  U31.z += P.z - r16.z;  U31.w += P.w - r16.w;
        U15.x += r7.x - r8.x;  U15.y += r7.y - r8.y;  U15.z += r7.z - r8.z;  U15.w += r7.w - r8.w;
        U3.x  += r1.x - rm2.x; U3.y  += r1.y - rm2.y; U3.z  += r1.z - rm2.z; U3.w  += r1.w - rm2.w;

        float4* wb = sUB + par * 3 * RW;
        wb[tid] = U31; wb[RW + tid] = U15; wb[2 * RW + tid] = U3;

        // consume row y-1 from previous parity
        if (i > 0 && cwv) {
            const float4* qb = sUB + (par ^ 1) * 3 * RW;
            float4 c31 = qb[tid - 4], a31 = qb[tid + 3], b31 = qb[tid + 4];
            float4 c15 = qb[RW + tid - 2], a15 = qb[RW + tid + 1], b15 = qb[RW + tid + 2];
            float4 d3  = qb[2 * RW + tid - 1], e3v = qb[2 * RW + tid], f3 = qb[2 * RW + tid + 1];

            float S31x = a31.w - c31.x, S31y = b31.x - c31.y, S31z = b31.y - c31.z, S31w = b31.z - c31.w;
            float S15x = a15.w - c15.x, S15y = b15.x - c15.y, S15z = b15.y - c15.z, S15w = b15.z - c15.w;
            float S3x  = e3v.y - d3.z,  S3y  = e3v.z - d3.w,  S3z  = e3v.w - e3v.x, S3w  = f3.x - e3v.y;

            int sc = (sp + 16) & 31;                       // slot(y-1)
            float4 rw = ringB[sc * RW + tid];
            float  lw = smf[(sc * RW + tid - 1) * 4 + 3];
            float m0 = rw.x - lw, m1 = rw.y - rw.x, m2 = rw.z - rw.y, m3 = rw.w - rw.z;

            epi(pO.x, m0, S3x, S15x, S31x, a0, a1, a2, a3, a4);
            epi(pO.y, m1, S3y, S15y, S31y, a0, a1, a2, a3, a4);
            epi(pO.z, m2, S3z, S15z, S31z, a0, a1, a2, a3, a4);
            epi(pO.w, m3, S3w, S15w, S31w, a0, a1, a2, a3, a4);
        }

        pO = pA2; pA2 = pB2; pB2 = pC;
        mA = mB; mB = mC;
        sp = (sp + 1) & 31;
        par ^= 1;
    }

    // ================= tail: consume row y0+rows-1 =================
    __syncthreads();
    if (cwv) {
        const float4* qb = sUB + (par ^ 1) * 3 * RW;
        float4 c31 = qb[tid - 4], a31 = qb[tid + 3], b31 = qb[tid + 4];
        float4 c15 = qb[RW + tid - 2], a15 = qb[RW + tid + 1], b15 = qb[RW + tid + 2];
        float4 d3  = qb[2 * RW + tid - 1], e3v = qb[2 * RW + tid], f3 = qb[2 * RW + tid + 1];

        float S31x = a31.w - c31.x, S31y = b31.x - c31.y, S31z = b31.y - c31.z, S31w = b31.z - c31.w;
        float S15x = a15.w - c15.x, S15y = b15.x - c15.y, S15z = b15.y - c15.z, S15w = b15.z - c15.w;
        float S3x  = e3v.y - d3.z,  S3y  = e3v.z - d3.w,  S3z  = e3v.w - e3v.x, S3w  = f3.x - e3v.y;

        int sc = (sp + 16) & 31;                           // slot(y0+rows-1)
        float4 rw = ringB[sc * RW + tid];
        float  lw = smf[(sc * RW + tid - 1) * 4 + 3];
        float m0 = rw.x - lw, m1 = rw.y - rw.x, m2 = rw.z - rw.y, m3 = rw.w - rw.z;

        epi(pO.x, m0, S3x, S15x, S31x, a0, a1, a2, a3, a4);
        epi(pO.y, m1, S3y, S15y, S31y, a0, a1, a2, a3, a4);
        epi(pO.z, m2, S3z, S15z, S31z, a0, a1, a2, a3, a4);
        epi(pO.w, m3, S3w, S15w, S31w, a0, a1, a2, a3, a4);
    }

    // ================= reduction + atomics =================
    #pragma unroll
    for (int d = 16; d > 0; d >>= 1) {
        a0 += __shfl_down_sync(0xffffffffu, a0, d);
        a1 += __shfl_down_sync(0xffffffffu, a1, d);
        a2 += __shfl_down_sync(0xffffffffu, a2, d);
        a3 += __shfl_down_sync(0xffffffffu, a3, d);
        a4 += __shfl_down_sync(0xffffffffu, a4, d);
    }
    if (lane == 0) {
        sred[warp * 5 + 0] = a0; sred[warp * 5 + 1] = a1; sred[warp * 5 + 2] = a2;
        sred[warp * 5 + 3] = a3; sred[warp * 5 + 4] = a4;
    }
    __syncthreads();
    if (warp == 0 && lane < 5) {
        float t = 0.f;
        #pragma unroll
        for (int wq = 0; wq < NWARP; ++wq) t += sred[wq * 5 + lane];
        atomicAdd(&g_accum[b * 5 + lane], t);
    }

    // ---- last-block finalize ----
    __threadfence();
    if (tid == 0) {
        unsigned int cdone = atomicAdd(&g_count, 1u);
        *sflag = (cdone == (unsigned int)(gridDim.x - 1)) ? 1u : 0u;
    }
    __syncthreads();
    if (*sflag && tid == 0) {
        float vals[BATCH * 5];
        #pragma unroll 1
        for (int i = 0; i < BATCH * 5; ++i) vals[i] = atomicAdd(&g_accum[i], 0.f);
        float mae_total = 0.f;
        for (int bb = 0; bb < BATCH; ++bb) mae_total += vals[bb * 5 + 4];
        const float mae = mae_total / (float)((long long)BATCH * HW);
        float acc = 0.f;
        for (int bb = 0; bb < BATCH; ++bb) {
            float ws = vals[bb * 5 + 0];
            float wb2 = vals[bb * 5 + 1];
            float it = vals[bb * 5 + 2];
            float un = vals[bb * 5 + 3];
            float wbce = wb2 / ws;
            float wiou = 1.f - (it + 1.f) / (un - it + 1.f);
            float wmae = mae * ws / (ws - (float)HW);
            acc += 0.7f * (wbce + wiou + wmae);
        }
        out[0] = acc / (float)BATCH;
        #pragma unroll 1
        for (int i = 0; i < BATCH * 5; ++i) g_accum[i] = 0.f;
        __threadfence();
        atomicExch(&g_count, 0u);
    }
}

extern "C" void kernel_launch(void* const* d_in, const int* in_sizes, int n_in,
                              void* d_out, int out_size) {
    const float* pred = (const float*)d_in[0];
    const float* mask = (const float*)d_in[1];
    float* out = (float*)d_out;

    const int smem_bytes = F4TOT * 16 + (16 + NWARP * 5 + 1) * 4;
    cudaFuncSetAttribute(adaptive_loss_main,
                         cudaFuncAttributeMaxDynamicSharedMemorySize, smem_bytes);
    adaptive_loss_main<<<NBLK, NT, smem_bytes>>>(pred, mask, out);
}

// round 10
// speedup vs baseline: 1.1171x; 1.1171x over previous
#include <cuda_runtime.h>

#define BATCH  16
#define H      1024
#define HW     (H*H)
#define NCHUNK 8
#define CHUNK  128            // 8*128 = 1024 exactly
#define NP     (CHUNK/2)      // 64 main iterations
#define NBLK   (BATCH*NCHUNK) // 128
#define RING   34
#define RW     260            // f4 per ring slot: [0]=left guard(0), [1..256]=data
#define SW     264            // f4 per U snapshot: [0..3]=0, [4..259]=data, [260..263]=flat
#define SUBASE (RING*RW)
#define F4TOT  (SUBASE + 12*SW)

__device__ float        g_accum[BATCH * 5];
__device__ unsigned int g_count;

__device__ __forceinline__ float4 f4z() { return make_float4(0.f, 0.f, 0.f, 0.f); }

__device__ __forceinline__ void epi(float x, float m, float S3, float S15, float S31,
                                    float& a0, float& a1, float& a2, float& a3, float& a4)
{
    float w = 1.f + 5.f * ( fabsf(S3  * (1.f / 9.f)   - m)
                          + fabsf(S15 * (1.f / 225.f) - m)
                          + fabsf(S31 * (1.f / 961.f) - m) );
    float e   = __expf(-fabsf(x));
    float l   = __logf(1.f + e);
    float bce = fmaxf(x, 0.f) - x * m + l;
    float inv = __fdividef(1.f, 1.f + e);
    float sg  = (x >= 0.f) ? inv : e * inv;
    a0 += w;
    a1 += w * bce;
    a2 += sg * m * w;
    a3 += (sg + m) * w;
    a4 += fabsf(sg - m);
}

__device__ __forceinline__ int subm(int s, int d) { int r = s - d; return (r < 0) ? r + RING : r; }

__global__ __launch_bounds__(256, 1) void adaptive_loss_main(
    const float* __restrict__ pred, const float* __restrict__ mask, float* __restrict__ out)
{
    extern __shared__ float4 sm4[];
    float*  smf   = (float*)sm4;
    float*  swsum = (float*)(sm4 + F4TOT);    // 32 floats (2 par x 2 rows x 8 warps), 16B aligned
    float*  sred  = swsum + 32;               // 8*5
    unsigned int* sflag = (unsigned int*)(sred + 40);

    const int tid  = threadIdx.x;             // owns cols 4*tid .. 4*tid+3
    const int lane = tid & 31;
    const int warp = tid >> 5;

    const int b  = blockIdx.x >> 3;
    const int c  = blockIdx.x & 7;
    const int y0 = c * CHUNK;

    const float4* mb4 = (const float4*)(mask + (size_t)b * HW);
    const float4* pb4 = (const float4*)(pred + (size_t)b * HW);

    // one-time guard init: 34 ring left-guards + 48 snapshot left-guards
    if (tid < RING) sm4[tid * RW] = f4z();
    else if (tid >= 64 && tid < 64 + 48) {
        int k = tid - 64;
        sm4[SUBASE + (k >> 2) * SW + (k & 3)] = f4z();
    }
    __syncthreads();

    float4 U31 = f4z(), U15 = f4z(), U3 = f4z();
    float a0 = 0.f, a1 = 0.f, a2 = 0.f, a3 = 0.f, a4 = 0.f;
    int par = 0;
    int sp = (y0 - 17 + 680) % RING;          // slot of next even write row (y0-17 first)

    // ================= priming: 16 pairs, rows y0-17 .. y0+14 =================
    float4 mR0, mR1;
    {
        int rA = y0 - 17, rB = y0 - 16;
        mR0 = (rA >= 0) ? mb4[(size_t)rA * 256 + tid] : f4z();
        mR1 = (rB >= 0) ? mb4[(size_t)rB * 256 + tid] : f4z();
    }
    #pragma unroll 1
    for (int j = 0; j < 16; ++j) {
        int rNa = y0 - 15 + 2 * j, rNb = rNa + 1;
        float4 mN0 = (rNa >= 0) ? mb4[(size_t)rNa * 256 + tid] : f4z();
        float4 mN1 = (rNb >= 0) ? mb4[(size_t)rNb * 256 + tid] : f4z();

        float4 v0 = mR0; v0.y += v0.x; v0.z += v0.y; v0.w += v0.z;
        float4 v1 = mR1; v1.y += v1.x; v1.z += v1.y; v1.w += v1.z;
        float t0 = v0.w, t1 = v1.w;
        #pragma unroll
        for (int d = 1; d < 32; d <<= 1) {
            float u0 = __shfl_up_sync(0xffffffffu, t0, d);
            float u1 = __shfl_up_sync(0xffffffffu, t1, d);
            if (lane >= d) { t0 += u0; t1 += u1; }
        }
        if (lane == 31) { swsum[par * 16 + warp] = t0; swsum[par * 16 + 8 + warp] = t1; }
        __syncthreads();
        const float4* sw4 = (const float4*)(swsum + par * 16);
        float4 q0 = sw4[0], q1 = sw4[1], q2 = sw4[2], q3 = sw4[3];
        float off0 = 0.f, off1 = 0.f;
        if (warp > 0) { off0 += q0.x; off1 += q2.x; }
        if (warp > 1) { off0 += q0.y; off1 += q2.y; }
        if (warp > 2) { off0 += q0.z; off1 += q2.z; }
        if (warp > 3) { off0 += q0.w; off1 += q2.w; }
        if (warp > 4) { off0 += q1.x; off1 += q3.x; }
        if (warp > 5) { off0 += q1.y; off1 += q3.y; }
        if (warp > 6) { off0 += q1.z; off1 += q3.z; }
        float b0 = off0 + (t0 - v0.w);
        float b1 = off1 + (t1 - v1.w);
        float4 P0 = make_float4(v0.x + b0, v0.y + b0, v0.z + b0, v0.w + b0);
        float4 P1 = make_float4(v1.x + b1, v1.y + b1, v1.z + b1, v1.w + b1);

        sm4[sp * RW + 1 + tid] = P0;
        int sp1 = sp + 1; if (sp1 >= RING) sp1 -= RING;
        sm4[sp1 * RW + 1 + tid] = P1;

        int rA = y0 - 17 + 2 * j, rB = rA + 1;
        if (rA >= y0 - 16) { U31.x += P0.x; U31.y += P0.y; U31.z += P0.z; U31.w += P0.w; }
        /* rB always in [y0-16, y0+14] */ { U31.x += P1.x; U31.y += P1.y; U31.z += P1.z; U31.w += P1.w; }
        if (rA >= y0 - 8 && rA <= y0 + 6) { U15.x += P0.x; U15.y += P0.y; U15.z += P0.z; U15.w += P0.w; }
        if (rB >= y0 - 8 && rB <= y0 + 6) { U15.x += P1.x; U15.y += P1.y; U15.z += P1.z; U15.w += P1.w; }
        if (rA >= y0 - 2 && rA <= y0)     { U3.x  += P0.x; U3.y  += P0.y; U3.z  += P0.z; U3.w  += P0.w; }
        if (rB >= y0 - 2 && rB <= y0)     { U3.x  += P1.x; U3.y  += P1.y; U3.z  += P1.z; U3.w  += P1.w; }

        mR0 = mN0; mR1 = mN1;
        sp += 2; if (sp >= RING) sp -= RING;
        par ^= 1;
    }
    // mR0,mR1 = raw mask rows y0+15, y0+16; sp = slot(y0+15); U centered at y0-1

    float4 pO0 = f4z(), pO1 = f4z(), pN0 = f4z(), pN1 = f4z();

    // ================= main: 64 iterations, 2 rows each =================
    #pragma unroll 1
    for (int i = 0; i < NP; ++i) {
        const int y = y0 + 2 * i;
        int ra = y + 17, rb = y + 18;
        float4 mN0 = (ra < H) ? mb4[(size_t)ra * 256 + tid] : f4z();
        float4 mN1 = (rb < H) ? mb4[(size_t)rb * 256 + tid] : f4z();
        float4 pL0 = pb4[(size_t)y * 256 + tid];
        float4 pL1 = pb4[(size_t)(y + 1) * 256 + tid];

        // ---- dual scan of rows y+15, y+16 ----
        float4 v0 = mR0; v0.y += v0.x; v0.z += v0.y; v0.w += v0.z;
        float4 v1 = mR1; v1.y += v1.x; v1.z += v1.y; v1.w += v1.z;
        float t0 = v0.w, t1 = v1.w;
        #pragma unroll
        for (int d = 1; d < 32; d <<= 1) {
            float u0 = __shfl_up_sync(0xffffffffu, t0, d);
            float u1 = __shfl_up_sync(0xffffffffu, t1, d);
            if (lane >= d) { t0 += u0; t1 += u1; }
        }
        if (lane == 31) { swsum[par * 16 + warp] = t0; swsum[par * 16 + 8 + warp] = t1; }
        __syncthreads();                                  // the ONLY barrier per 2 rows
        const float4* sw4 = (const float4*)(swsum + par * 16);
        float4 q0 = sw4[0], q1 = sw4[1], q2 = sw4[2], q3 = sw4[3];
        float off0 = 0.f, off1 = 0.f;
        if (warp > 0) { off0 += q0.x; off1 += q2.x; }
        if (warp > 1) { off0 += q0.y; off1 += q2.y; }
        if (warp > 2) { off0 += q0.z; off1 += q2.z; }
        if (warp > 3) { off0 += q0.w; off1 += q2.w; }
        if (warp > 4) { off0 += q1.x; off1 += q3.x; }
        if (warp > 5) { off0 += q1.y; off1 += q3.y; }
        if (warp > 6) { off0 += q1.z; off1 += q3.z; }
        float b0 = off0 + (t0 - v0.w);
        float b1 = off1 + (t1 - v1.w);
        float4 P0 = make_float4(v0.x + b0, v0.y + b0, v0.z + b0, v0.w + b0);
        float4 P1 = make_float4(v1.x + b1, v1.y + b1, v1.z + b1, v1.w + b1);

        sm4[sp * RW + 1 + tid] = P0;                      // P(y+15)
        int sp1 = sp + 1; if (sp1 >= RING) sp1 -= RING;
        sm4[sp1 * RW + 1 + tid] = P1;                     // P(y+16)

        // ---- ring reads for U updates ----
        int s16 = subm(sp, 31), s17 = subm(sp, 32);
        int s7p = subm(sp, 8),  s8m = subm(sp, 23);
        int s8p = subm(sp, 7),  s7m = subm(sp, 22);
        int s1p = subm(sp, 14), s2m = subm(sp, 17);
        int s2p = subm(sp, 13), s1m = subm(sp, 16);

        float4 r16 = sm4[s16 * RW + 1 + tid], r17 = sm4[s17 * RW + 1 + tid];
        float4 r7p = sm4[s7p * RW + 1 + tid], r8m = sm4[s8m * RW + 1 + tid];
        float4 r8p = sm4[s8p * RW + 1 + tid], r7m = sm4[s7m * RW + 1 + tid];
        float4 r1p = sm4[s1p * RW + 1 + tid], r2m = sm4[s2m * RW + 1 + tid];
        float4 r2p = sm4[s2p * RW + 1 + tid], r1m = sm4[s1m * RW + 1 + tid];

        float4 U31a, U31b, U15a, U15b, U3a, U3b;
        U31a.x = U31.x + P0.x - r16.x; U31a.y = U31.y + P0.y - r16.y;
        U31a.z = U31.z + P0.z - r16.z; U31a.w = U31.w + P0.w - r16.w;
        U31b.x = U31a.x + P1.x - r17.x; U31b.y = U31a.y + P1.y - r17.y;
        U31b.z = U31a.z + P1.z - r17.z; U31b.w = U31a.w + P1.w - r17.w;
        U15a.x = U15.x + r7p.x - r8m.x; U15a.y = U15.y + r7p.y - r8m.y;
        U15a.z = U15.z + r7p.z - r8m.z; U15a.w = U15.w + r7p.w - r8m.w;
        U15b.x = U15a.x + r8p.x - r7m.x; U15b.y = U15a.y + r8p.y - r7m.y;
        U15b.z = U15a.z + r8p.z - r7m.z; U15b.w = U15a.w + r8p.w - r7m.w;
        U3a.x = U3.x + r1p.x - r2m.x; U3a.y = U3.y + r1p.y - r2m.y;
        U3a.z = U3.z + r1p.z - r2m.z; U3a.w = U3.w + r1p.w - r2m.w;
        U3b.x = U3a.x + r2p.x - r1m.x; U3b.y = U3a.y + r2p.y - r1m.y;
        U3b.z = U3a.z + r2p.z - r1m.z; U3b.w = U3a.w + r2p.w - r1m.w;
        U31 = U31b; U15 = U15b; U3 = U3b;

        const int base = SUBASE + par * 6 * SW;
        sm4[base + 0 * SW + 4 + tid] = U31a;
        sm4[base + 1 * SW + 4 + tid] = U15a;
        sm4[base + 2 * SW + 4 + tid] = U3a;
        sm4[base + 3 * SW + 4 + tid] = U31b;
        sm4[base + 4 * SW + 4 + tid] = U15b;
        sm4[base + 5 * SW + 4 + tid] = U3b;
        if (warp == 7) {
            float g0 = __shfl_sync(0xffffffffu, U31a.w, 31);
            float g1 = __shfl_sync(0xffffffffu, U15a.w, 31);
            float g2 = __shfl_sync(0xffffffffu, U3a.w,  31);
            float g3 = __shfl_sync(0xffffffffu, U31b.w, 31);
            float g4 = __shfl_sync(0xffffffffu, U15b.w, 31);
            float g5 = __shfl_sync(0xffffffffu, U3b.w,  31);
            if (lane < 24) {
                int arr = lane >> 2, word = lane & 3;
                float qq = (arr == 0) ? g0 : (arr == 1) ? g1 : (arr == 2) ? g2
                         : (arr == 3) ? g3 : (arr == 4) ? g4 : g5;
                sm4[base + arr * SW + 260 + word] = make_float4(qq, qq, qq, qq);
            }
        }

        // ---- consume pair (y-2, y-1) from previous parity ----
        if (i > 0) {
            const int qb = SUBASE + (par ^ 1) * 6 * SW;
            #pragma unroll
            for (int r = 0; r < 2; ++r) {
                const int rbq = qb + r * 3 * SW;
                float4 c31 = sm4[rbq + tid],          a31 = sm4[rbq + tid + 7],      b31v = sm4[rbq + tid + 8];
                float4 c15 = sm4[rbq + SW + tid + 2], a15 = sm4[rbq + SW + tid + 5], b15v = sm4[rbq + SW + tid + 6];
                float4 d3  = sm4[rbq + 2*SW + tid + 3], e3v = sm4[rbq + 2*SW + tid + 4], f3 = sm4[rbq + 2*SW + tid + 5];

                float S31x = a31.w - c31.x, S31y = b31v.x - c31.y, S31z = b31v.y - c31.z, S31w = b31v.z - c31.w;
                float S15x = a15.w - c15.x, S15y = b15v.x - c15.y, S15z = b15v.y - c15.z, S15w = b15v.z - c15.w;
                float S3x  = e3v.y - d3.z,  S3y  = e3v.z - d3.w,  S3z  = e3v.w - e3v.x, S3w  = f3.x - e3v.y;

                float4 rw = (r == 0) ? r2m : r1m;           // P(y-2) / P(y-1) already loaded
                int    sc = (r == 0) ? s2m : s1m;
                float  lw = smf[(sc * RW + tid) * 4 + 3];
                float m0 = rw.x - lw, m1 = rw.y - rw.x, m2 = rw.z - rw.y, m3 = rw.w - rw.z;
                float4 px = (r == 0) ? pO0 : pO1;

                epi(px.x, m0, S3x, S15x, S31x, a0, a1, a2, a3, a4);
                epi(px.y, m1, S3y, S15y, S31y, a0, a1, a2, a3, a4);
                epi(px.z, m2, S3z, S15z, S31z, a0, a1, a2, a3, a4);
                epi(px.w, m3, S3w, S15w, S31w, a0, a1, a2, a3, a4);
            }
        }

        pO0 = pL0; pO1 = pL1;
        mR0 = mN0; mR1 = mN1;
        sp += 2; if (sp >= RING) sp -= RING;
        par ^= 1;
    }

    // ================= tail: consume pair (y0+126, y0+127) =================
    __syncthreads();
    {
        const int qb = SUBASE + (par ^ 1) * 6 * SW;
        int sc0 = subm(sp, 17), sc1 = subm(sp, 16);
        #pragma unroll
        for (int r = 0; r < 2; ++r) {
            const int rbq = qb + r * 3 * SW;
            float4 c31 = sm4[rbq + tid],          a31 = sm4[rbq + tid + 7],      b31v = sm4[rbq + tid + 8];
            float4 c15 = sm4[rbq + SW + tid + 2], a15 = sm4[rbq + SW + tid + 5], b15v = sm4[rbq + SW + tid + 6];
            float4 d3  = sm4[rbq + 2*SW + tid + 3], e3v = sm4[rbq + 2*SW + tid + 4], f3 = sm4[rbq + 2*SW + tid + 5];

            float S31x = a31.w - c31.x, S31y = b31v.x - c31.y, S31z = b31v.y - c31.z, S31w = b31v.z - c31.w;
            float S15x = a15.w - c15.x, S15y = b15v.x - c15.y, S15z = b15v.y - c15.z, S15w = b15v.z - c15.w;
            float S3x  = e3v.y - d3.z,  S3y  = e3v.z - d3.w,  S3z  = e3v.w - e3v.x, S3w  = f3.x - e3v.y;

            int sc = (r == 0) ? sc0 : sc1;
            float4 rw = sm4[sc * RW + 1 + tid];
            float  lw = smf[(sc * RW + tid) * 4 + 3];
            float m0 = rw.x - lw, m1 = rw.y - rw.x, m2 = rw.z - rw.y, m3 = rw.w - rw.z;
            float4 px = (r == 0) ? pO0 : pO1;

            epi(px.x, m0, S3x, S15x, S31x, a0, a1, a2, a3, a4);
            epi(px.y, m1, S3y, S15y, S31y, a0, a1, a2, a3, a4);
            epi(px.z, m2, S3z, S15z, S31z, a0, a1, a2, a3, a4);
            epi(px.w, m3, S3w, S15w, S31w, a0, a1, a2, a3, a4);
        }
    }

    // ================= reduction + atomics =================
    #pragma unroll
    for (int d = 16; d > 0; d >>= 1) {
        a0 += __shfl_down_sync(0xffffffffu, a0, d);
        a1 += __shfl_down_sync(0xffffffffu, a1, d);
        a2 += __shfl_down_sync(0xffffffffu, a2, d);
        a3 += __shfl_down_sync(0xffffffffu, a3, d);
        a4 += __shfl_down_sync(0xffffffffu, a4, d);
    }
    if (lane == 0) {
        sred[warp * 5 + 0] = a0; sred[warp * 5 + 1] = a1; sred[warp * 5 + 2] = a2;
        sred[warp * 5 + 3] = a3; sred[warp * 5 + 4] = a4;
    }
    __syncthreads();
    if (warp == 0 && lane < 5) {
        float t = 0.f;
        #pragma unroll
        for (int wq = 0; wq < 8; ++wq) t += sred[wq * 5 + lane];
        atomicAdd(&g_accum[b * 5 + lane], t);
    }

    // ---- last-block finalize ----
    __threadfence();
    if (tid == 0) {
        unsigned int cdone = atomicAdd(&g_count, 1u);
        *sflag = (cdone == (unsigned int)(gridDim.x - 1)) ? 1u : 0u;
    }
    __syncthreads();
    if (*sflag && tid == 0) {
        float vals[BATCH * 5];
        #pragma unroll 1
        for (int i = 0; i < BATCH * 5; ++i) vals[i] = atomicAdd(&g_accum[i], 0.f);
        float mae_total = 0.f;
        for (int bb = 0; bb < BATCH; ++bb) mae_total += vals[bb * 5 + 4];
        const float mae = mae_total / (float)((long long)BATCH * HW);
        float acc = 0.f;
        for (int bb = 0; bb < BATCH; ++bb) {
            float ws = vals[bb * 5 + 0];
            float wb = vals[bb * 5 + 1];
            float it = vals[bb * 5 + 2];
            float un = vals[bb * 5 + 3];
            float wbce = wb / ws;
            float wiou = 1.f - (it + 1.f) / (un - it + 1.f);
            float wmae = mae * ws / (ws - (float)HW);
            acc += 0.7f * (wbce + wiou + wmae);
        }
        out[0] = acc / (float)BATCH;
        #pragma unroll 1
        for (int i = 0; i < BATCH * 5; ++i) g_accum[i] = 0.f;
        __threadfence();
        atomicExch(&g_count, 0u);
    }
}

extern "C" void kernel_launch(void* const* d_in, const int* in_sizes, int n_in,
                              void* d_out, int out_size) {
    const float* pred = (const float*)d_in[0];
    const float* mask = (const float*)d_in[1];
    float* out = (float*)d_out;

    const int smem_bytes = F4TOT * 16 + (32 + 40 + 1) * 4;
    cudaFuncSetAttribute(adaptive_loss_main,
                         cudaFuncAttributeMaxDynamicSharedMemorySize, smem_bytes);
    adaptive_loss_main<<<NBLK, 256, smem_bytes>>>(pred, mask, out);
}

// round 11
// speedup vs baseline: 1.1493x; 1.0288x over previous
#include <cuda_runtime.h>

#define BATCH  16
#define H      1024
#define HW     (H*H)
#define NSTRIP 5
#define NBANDS 11
#define BANDH  94
#define TASKS  (BATCH*NSTRIP*NBANDS)   // 880
#define WPB    6
#define NT     192
#define NCTA   ((TASKS+WPB-1)/WPB)     // 147
#define RINGF4 2048                    // 32 slots x (E[32]+O[32]) f4
#define WARPF4 2304                    // + 2 parities x 128 f4 snapshots

__device__ float        g_accum[BATCH * 5];
__device__ unsigned int g_count;

__device__ __forceinline__ float4 f4z() { return make_float4(0.f, 0.f, 0.f, 0.f); }
__device__ __forceinline__ void addf4(float4& a, const float4 b) { a.x+=b.x; a.y+=b.y; a.z+=b.z; a.w+=b.w; }

__device__ __forceinline__ void epi(float x, float m, float S3, float S15, float S31,
                                    float& a0, float& a1, float& a2, float& a3, float& a4)
{
    float w = 1.f + 5.f * ( fabsf(S3  * (1.f / 9.f)   - m)
                          + fabsf(S15 * (1.f / 225.f) - m)
                          + fabsf(S31 * (1.f / 961.f) - m) );
    float e   = __expf(-fabsf(x));
    float l   = __logf(1.f + e);
    float bce = fmaxf(x, 0.f) - x * m + l;
    float inv = __fdividef(1.f, 1.f + e);
    float sg  = (x >= 0.f) ? inv : e * inv;
    a0 += w;
    a1 += w * bce;
    a2 += sg * m * w;
    a3 += (sg + m) * w;
    a4 += fabsf(sg - m);
}

__global__ __launch_bounds__(NT, 1) void adaptive_loss_main(
    const float* __restrict__ pred, const float* __restrict__ mask, float* __restrict__ out)
{
    extern __shared__ float4 sm4[];
    unsigned int* sflag = (unsigned int*)(sm4 + WPB * WARPF4);
    const int tid  = threadIdx.x;
    const int lane = tid & 31;
    const int warp = tid >> 5;
    const int task = blockIdx.x * WPB + warp;

    float a0 = 0.f, a1 = 0.f, a2 = 0.f, a3 = 0.f, a4 = 0.f;
    int b = 0;

    if (task < TASKS) {
        b = task / (NSTRIP * NBANDS);
        const int rem  = task % (NSTRIP * NBANDS);
        const int s    = rem / NBANDS;
        const int band = rem % NBANDS;
        const int y0   = band * BANDH;
        const int rows = (H - y0 < BANDH) ? (H - y0) : BANDH;

        const float4* mb4 = (const float4*)(mask + (size_t)b * HW);
        const float4* pb4 = (const float4*)(pred + (size_t)b * HW);

        // lane owns local cols 8*lane .. 8*lane+7 of a 256-col window starting at 224*s - 16
        const int  wE  = 56 * s - 4 + 2 * lane;     // global f4 word (even)
        const int  wO  = wE + 1;
        const bool okE = ((unsigned)wE < 256u);
        const bool okO = ((unsigned)wO < 256u);
        const bool dataT = (lane >= 2) && (lane <= 29) && ((224 * s + 8 * (lane - 2)) < 1024);

        float4* rg = sm4 + warp * WARPF4;           // ring: slot*64 + {lane | 32+lane}
        float4* sn = rg + RINGF4;                   // snapshots: par*128 + {0,32,64,96}+lane

        float4 U31a = f4z(), U31b = f4z(), U15a = f4z(), U15b = f4z(), U3a = f4z(), U3b = f4z();

        // ---------- priming: rows y0-16 .. y0+14 ----------
        float4 mE, mO;
        {
            int r = y0 - 16; bool ok = (r >= 0);
            mE = (ok && okE) ? mb4[(size_t)r * 256 + wE] : f4z();
            mO = (ok && okO) ? mb4[(size_t)r * 256 + wO] : f4z();
        }
        #pragma unroll 1
        for (int j = 0; j < 31; ++j) {
            const int r = y0 - 16 + j, rn = r + 1;
            const bool okn = (rn >= 0) && (rn < H);
            float4 nE = (okn && okE) ? mb4[(size_t)rn * 256 + wE] : f4z();
            float4 nO = (okn && okO) ? mb4[(size_t)rn * 256 + wO] : f4z();

            float4 v0 = mE; v0.y += v0.x; v0.z += v0.y; v0.w += v0.z;
            float4 v1 = mO; v1.y += v1.x; v1.z += v1.y; v1.w += v1.z;
            v1.x += v0.w; v1.y += v0.w; v1.z += v0.w; v1.w += v0.w;
            float tot = v1.w;
            #pragma unroll
            for (int d = 1; d < 32; d <<= 1) {
                float u = __shfl_up_sync(0xffffffffu, tot, d);
                if (lane >= d) tot += u;
            }
            const float ex = tot - v1.w;
            float4 P0 = make_float4(v0.x + ex, v0.y + ex, v0.z + ex, v0.w + ex);
            float4 P1 = make_float4(v1.x + ex, v1.y + ex, v1.z + ex, v1.w + ex);
            const int sl = (r + 512) & 31;
            rg[sl * 64 + lane]      = P0;
            rg[sl * 64 + 32 + lane] = P1;

            addf4(U31a, P0); addf4(U31b, P1);
            if (j >= 8  && j <= 22) { addf4(U15a, P0); addf4(U15b, P1); }
            if (j >= 14 && j <= 16) { addf4(U3a,  P0); addf4(U3b,  P1); }

            mE = nE; mO = nO;
        }
        // mE/mO = raw mask row y0+15; U centered at y0-1

        float4 pE = f4z(), pO = f4z();
        if (dataT) { pE = pb4[(size_t)y0 * 256 + wE]; pO = pb4[(size_t)y0 * 256 + wO]; }

        // ---------- main: consume row y in the same iteration ----------
        #pragma unroll 1
        for (int i = 0; i < rows; ++i) {
            const int y  = y0 + i;
            const int rn = y + 16;
            float4 nE = (rn < H && okE) ? mb4[(size_t)rn * 256 + wE] : f4z();
            float4 nO = (rn < H && okO) ? mb4[(size_t)rn * 256 + wO] : f4z();
            float4 qE = f4z(), qO = f4z();
            if (dataT && (y + 1 < H)) {
                qE = pb4[(size_t)(y + 1) * 256 + wE];
                qO = pb4[(size_t)(y + 1) * 256 + wO];
            }

            // warp-local scan of mask row y+15
            float4 v0 = mE; v0.y += v0.x; v0.z += v0.y; v0.w += v0.z;
            float4 v1 = mO; v1.y += v1.x; v1.z += v1.y; v1.w += v1.z;
            v1.x += v0.w; v1.y += v0.w; v1.z += v0.w; v1.w += v0.w;
            float tot = v1.w;
            #pragma unroll
            for (int d = 1; d < 32; d <<= 1) {
                float u = __shfl_up_sync(0xffffffffu, tot, d);
                if (lane >= d) tot += u;
            }
            const float ex = tot - v1.w;
            float4 P0 = make_float4(v0.x + ex, v0.y + ex, v0.z + ex, v0.w + ex);
            float4 P1 = make_float4(v1.x + ex, v1.y + ex, v1.z + ex, v1.w + ex);

            const int sp = (y + 15 + 512) & 31;
            rg[sp * 64 + lane]      = P0;
            rg[sp * 64 + 32 + lane] = P1;

            const int sl16 = (y - 16 + 512) & 31, sl7 = (y + 7 + 512) & 31, sl8 = (y - 8 + 512) & 31;
            const int sl1  = (y + 1 + 512) & 31,  sl2 = (y - 2 + 512) & 31, sly = (y + 512) & 31;

            float4 t16E = rg[sl16 * 64 + lane], t16O = rg[sl16 * 64 + 32 + lane];
            float4 t7E  = rg[sl7  * 64 + lane], t7O  = rg[sl7  * 64 + 32 + lane];
            float4 t8E  = rg[sl8  * 64 + lane], t8O  = rg[sl8  * 64 + 32 + lane];
            float4 t1E  = rg[sl1  * 64 + lane], t1O  = rg[sl1  * 64 + 32 + lane];
            float4 t2E  = rg[sl2  * 64 + lane], t2O  = rg[sl2  * 64 + 32 + lane];

            U31a.x += P0.x - t16E.x; U31a.y += P0.y - t16E.y; U31a.z += P0.z - t16E.z; U31a.w += P0.w - t16E.w;
            U31b.x += P1.x - t16O.x; U31b.y += P1.y - t16O.y; U31b.z += P1.z - t16O.z; U31b.w += P1.w - t16O.w;
            U15a.x += t7E.x - t8E.x; U15a.y += t7E.y - t8E.y; U15a.z += t7E.z - t8E.z; U15a.w += t7E.w - t8E.w;
            U15b.x += t7O.x - t8O.x; U15b.y += t7O.y - t8O.y; U15b.z += t7O.z - t8O.z; U15b.w += t7O.w - t8O.w;
            U3a.x  += t1E.x - t2E.x; U3a.y  += t1E.y - t2E.y; U3a.z  += t1E.z - t2E.z; U3a.w  += t1E.w - t2E.w;
            U3b.x  += t1O.x - t2O.x; U3b.y  += t1O.y - t2O.y; U3b.z  += t1O.z - t2O.z; U3b.w  += t1O.w - t2O.w;

            const int par = (i & 1) * 128;
            sn[par + lane]      = U31a;
            sn[par + 32 + lane] = U31b;
            sn[par + 64 + lane] = U15a;
            sn[par + 96 + lane] = U15b;

            // k=3 cross-lane values (uniform warp execution, before divergence)
            float pz = __shfl_up_sync(0xffffffffu, U3b.z, 1);     // U3(8L-2)
            float pw = __shfl_up_sync(0xffffffffu, U3b.w, 1);     // U3(8L-1)
            float nx = __shfl_down_sync(0xffffffffu, U3a.x, 1);   // U3(8L+8)

            __syncwarp();

            if (dataT) {
                float4 o31p = sn[par + 32 + lane + 1];
                float4 e31p = sn[par + lane + 2];
                float4 o31q = sn[par + 32 + lane + 2];
                float4 e31m = sn[par + lane - 2];
                float4 o31m = sn[par + 32 + lane - 2];
                float4 e15p = sn[par + 64 + lane + 1];
                float4 o15p = sn[par + 96 + lane + 1];
                float4 e15m = sn[par + 64 + lane - 1];
                float4 o15m = sn[par + 96 + lane - 1];

                float4 mEr = rg[sly * 64 + lane];
                float4 mOr = rg[sly * 64 + 32 + lane];
                float4 mLm = rg[sly * 64 + 32 + lane - 1];
                float m0 = mEr.x - mLm.w, m1 = mEr.y - mEr.x, m2 = mEr.z - mEr.y, m3 = mEr.w - mEr.z;
                float m4 = mOr.x - mEr.w, m5 = mOr.y - mOr.x, m6 = mOr.z - mOr.y, m7 = mOr.w - mOr.z;

                epi(pE.x, m0, U3a.y - pz,    U15b.w - e15m.x, o31p.w - e31m.x, a0, a1, a2, a3, a4);
                epi(pE.y, m1, U3a.z - pw,    e15p.x - e15m.y, e31p.x - e31m.y, a0, a1, a2, a3, a4);
                epi(pE.z, m2, U3a.w - U3a.x, e15p.y - e15m.z, e31p.y - e31m.z, a0, a1, a2, a3, a4);
                epi(pE.w, m3, U3b.x - U3a.y, e15p.z - e15m.w, e31p.z - e31m.w, a0, a1, a2, a3, a4);
                epi(pO.x, m4, U3b.y - U3a.z, e15p.w - o15m.x, e31p.w - o31m.x, a0, a1, a2, a3, a4);
                epi(pO.y, m5, U3b.z - U3a.w, o15p.x - o15m.y, o31q.x - o31m.y, a0, a1, a2, a3, a4);
                epi(pO.z, m6, U3b.w - U3b.x, o15p.y - o15m.z, o31q.y - o31m.z, a0, a1, a2, a3, a4);
                epi(pO.w, m7, nx - U3b.y,    o15p.z - o15m.w, o31q.z - o31m.w, a0, a1, a2, a3, a4);
            }

            mE = nE; mO = nO; pE = qE; pO = qO;
        }

        // warp reduce + per-warp atomics (warps may belong to different images)
        #pragma unroll
        for (int d = 16; d > 0; d >>= 1) {
            a0 += __shfl_down_sync(0xffffffffu, a0, d);
            a1 += __shfl_down_sync(0xffffffffu, a1, d);
            a2 += __shfl_down_sync(0xffffffffu, a2, d);
            a3 += __shfl_down_sync(0xffffffffu, a3, d);
            a4 += __shfl_down_sync(0xffffffffu, a4, d);
        }
        if (lane == 0) {
            atomicAdd(&g_accum[b * 5 + 0], a0);
            atomicAdd(&g_accum[b * 5 + 1], a1);
            atomicAdd(&g_accum[b * 5 + 2], a2);
            atomicAdd(&g_accum[b * 5 + 3], a3);
            atomicAdd(&g_accum[b * 5 + 4], a4);
        }
    }

    // ---- last-block finalize ----
    __threadfence();
    __syncthreads();
    if (tid == 0) {
        unsigned int cdone = atomicAdd(&g_count, 1u);
        *sflag = (cdone == (unsigned int)(gridDim.x - 1)) ? 1u : 0u;
    }
    __syncthreads();
    if (*sflag && tid == 0) {
        float vals[BATCH * 5];
        #pragma unroll 1
        for (int i = 0; i < BATCH * 5; ++i) vals[i] = atomicAdd(&g_accum[i], 0.f);
        float mae_total = 0.f;
        for (int bb = 0; bb < BATCH; ++bb) mae_total += vals[bb * 5 + 4];
        const float mae = mae_total / (float)((long long)BATCH * HW);
        float acc = 0.f;
        for (int bb = 0; bb < BATCH; ++bb) {
            float ws = vals[bb * 5 + 0];
            float wb = vals[bb * 5 + 1];
            float it = vals[bb * 5 + 2];
            float un = vals[bb * 5 + 3];
            float wbce = wb / ws;
            float wiou = 1.f - (it + 1.f) / (un - it + 1.f);
            float wmae = mae * ws / (ws - (float)HW);
            acc += 0.7f * (wbce + wiou + wmae);
        }
        out[0] = acc / (float)BATCH;
        #pragma unroll 1
        for (int i = 0; i < BATCH * 5; ++i) g_accum[i] = 0.f;
        __threadfence();
        atomicExch(&g_count, 0u);
    }
}

extern "C" void kernel_launch(void* const* d_in, const int* in_sizes, int n_in,
                              void* d_out, int out_size) {
    const float* pred = (const float*)d_in[0];
    const float* mask = (const float*)d_in[1];
    float* out = (float*)d_out;

    const int smem_bytes = WPB * WARPF4 * 16 + 16;
    cudaFuncSetAttribute(adaptive_loss_main,
                         cudaFuncAttributeMaxDynamicSharedMemorySize, smem_bytes);
    adaptive_loss_main<<<NCTA, NT, smem_bytes>>>(pred, mask, out);
}

// round 12
// speedup vs baseline: 1.4855x; 1.2925x over previous
#include <cuda_runtime.h>

#define BATCH  16
#define H      1024
#define HW     (H*H)
#define NSTRIP 11
#define NBANDS 10
#define BANDH  103
#define TASKS  (BATCH*NSTRIP*NBANDS)   // 1760
#define WPB    12
#define NT     384
#define NCTA   ((TASKS+WPB-1)/WPB)     // 147
#define WARPF4 1088                    // ring 32 slots x 32 f4 + snU31[32] + snU15[32]

__device__ float        g_accum[BATCH * 5];
__device__ unsigned int g_count;

__device__ __forceinline__ float4 f4z() { return make_float4(0.f, 0.f, 0.f, 0.f); }
__device__ __forceinline__ void addf4(float4& a, const float4 b) { a.x+=b.x; a.y+=b.y; a.z+=b.z; a.w+=b.w; }

__device__ __forceinline__ void epi(float x, float m, float S3, float S15, float S31,
                                    float& a0, float& a1, float& a2, float& a3, float& a4)
{
    float w = 1.f + 5.f * ( fabsf(S3  * (1.f / 9.f)   - m)
                          + fabsf(S15 * (1.f / 225.f) - m)
                          + fabsf(S31 * (1.f / 961.f) - m) );
    float e   = __expf(-fabsf(x));
    float l   = __logf(1.f + e);
    float bce = fmaxf(x, 0.f) - x * m + l;
    float inv = __fdividef(1.f, 1.f + e);
    float sg  = (x >= 0.f) ? inv : e * inv;
    a0 += w;
    a1 += w * bce;
    a2 += sg * m * w;
    a3 += (sg + m) * w;
    a4 += fabsf(sg - m);
}

__global__ __launch_bounds__(NT, 1) void adaptive_loss_main(
    const float* __restrict__ pred, const float* __restrict__ mask, float* __restrict__ out)
{
    extern __shared__ float4 sm4[];
    unsigned int* sflag = (unsigned int*)(sm4 + WPB * WARPF4);
    const int tid  = threadIdx.x;
    const int lane = tid & 31;
    const int warp = tid >> 5;
    const int task = blockIdx.x * WPB + warp;

    float a0 = 0.f, a1 = 0.f, a2 = 0.f, a3 = 0.f, a4 = 0.f;
    int b = 0;

    if (task < TASKS) {
        b = task / (NSTRIP * NBANDS);
        const int rem  = task % (NSTRIP * NBANDS);
        const int s    = rem / NBANDS;
        const int band = rem % NBANDS;
        const int y0   = band * BANDH;
        const int rows = (H - y0 < BANDH) ? (H - y0) : BANDH;

        const float4* mb4 = (const float4*)(mask + (size_t)b * HW);
        const float4* pb4 = (const float4*)(pred + (size_t)b * HW);

        // lane owns 1 f4 word: window words 24s-4 .. 24s+27 (128 cols, 96 data)
        const int  w   = 24 * s - 4 + lane;
        const bool ok  = ((unsigned)w < 256u);
        const bool dataT = (lane >= 4) && (lane <= 27) && ((24 * s + lane - 4) < 256);

        float4* rg  = sm4 + warp * WARPF4;    // ring: slot*32 + lane
        float4* s31 = rg + 1024;              // U31 snapshot [32]
        float4* s15 = rg + 1056;              // U15 snapshot [32]

        float4 U31 = f4z(), U15 = f4z(), U3 = f4z();

        // ---------- priming: rows y0-16 .. y0+14 ----------
        float4 mCur;
        {
            int r = y0 - 16;
            mCur = (r >= 0 && ok) ? mb4[(size_t)r * 256 + w] : f4z();
        }
        #pragma unroll 1
        for (int j = 0; j < 31; ++j) {
            const int r = y0 - 16 + j, rn = r + 1;
            float4 mN = (rn >= 0 && rn < H && ok) ? mb4[(size_t)rn * 256 + w] : f4z();

            float4 v = mCur; v.y += v.x; v.z += v.y; v.w += v.z;
            float tot = v.w;
            #pragma unroll
            for (int d = 1; d < 32; d <<= 1) {
                float u = __shfl_up_sync(0xffffffffu, tot, d);
                if (lane >= d) tot += u;
            }
            const float ex = tot - v.w;
            float4 P = make_float4(v.x + ex, v.y + ex, v.z + ex, v.w + ex);
            rg[((r + 512) & 31) * 32 + lane] = P;

            addf4(U31, P);
            if (j >= 8  && j <= 22) addf4(U15, P);
            if (j >= 14 && j <= 16) addf4(U3,  P);

            mCur = mN;
        }
        // mCur = raw mask row y0+15; U centered at y0-1

        float4 pCur = dataT ? pb4[(size_t)y0 * 256 + w] : f4z();

        // ---------- main ----------
        #pragma unroll 1
        for (int i = 0; i < rows; ++i) {
            const int y  = y0 + i;
            const int rn = y + 16;
            float4 mN = (rn < H && ok) ? mb4[(size_t)rn * 256 + w] : f4z();
            float4 pN = (dataT && (y + 1 < H)) ? pb4[(size_t)(y + 1) * 256 + w] : f4z();

            // warp-local scan of mask row y+15
            float4 v = mCur; v.y += v.x; v.z += v.y; v.w += v.z;
            float tot = v.w;
            #pragma unroll
            for (int d = 1; d < 32; d <<= 1) {
                float u = __shfl_up_sync(0xffffffffu, tot, d);
                if (lane >= d) tot += u;
            }
            const float ex = tot - v.w;
            float4 P = make_float4(v.x + ex, v.y + ex, v.z + ex, v.w + ex);
            rg[((y + 15) & 31) * 32 + lane] = P;

            // vertical running sums — own-lane ring taps
            float4 t16 = rg[((y - 16 + 512) & 31) * 32 + lane];
            float4 t7  = rg[((y + 7)        & 31) * 32 + lane];
            float4 t8  = rg[((y - 8 + 512)  & 31) * 32 + lane];
            float4 t1  = rg[((y + 1)        & 31) * 32 + lane];
            float4 t2  = rg[((y - 2 + 512)  & 31) * 32 + lane];

            U31.x += P.x - t16.x; U31.y += P.y - t16.y; U31.z += P.z - t16.z; U31.w += P.w - t16.w;
            U15.x += t7.x - t8.x; U15.y += t7.y - t8.y; U15.z += t7.z - t8.z; U15.w += t7.w - t8.w;
            U3.x  += t1.x - t2.x; U3.y  += t1.y - t2.y; U3.z  += t1.z - t2.z; U3.w  += t1.w - t2.w;

            s31[lane] = U31;
            s15[lane] = U15;

            // k=3 cross-lane values (uniform execution)
            float uz = __shfl_up_sync(0xffffffffu, U3.z, 1);      // U3(4L-2)
            float uw = __shfl_up_sync(0xffffffffu, U3.w, 1);      // U3(4L-1)
            float dx = __shfl_down_sync(0xffffffffu, U3.x, 1);    // U3(4L+4)

            __syncwarp();

            if (dataT) {
                float4 a31 = s31[lane + 3], b31 = s31[lane + 4], c31 = s31[lane - 4];
                float4 a15 = s15[lane + 1], b15 = s15[lane + 2], c15 = s15[lane - 2];

                const int sly = y & 31;
                float4 mEr = rg[sly * 32 + lane];
                float  mLw = rg[sly * 32 + lane - 1].w;
                float m0 = mEr.x - mLw,   m1 = mEr.y - mEr.x;
                float m2 = mEr.z - mEr.y, m3 = mEr.w - mEr.z;

                epi(pCur.x, m0, U3.y - uz,   a15.w - c15.x, a31.w - c31.x, a0, a1, a2, a3, a4);
                epi(pCur.y, m1, U3.z - uw,   b15.x - c15.y, b31.x - c31.y, a0, a1, a2, a3, a4);
                epi(pCur.z, m2, U3.w - U3.x, b15.y - c15.z, b31.y - c31.z, a0, a1, a2, a3, a4);
                epi(pCur.w, m3, dx - U3.y,   b15.z - c15.w, b31.z - c31.w, a0, a1, a2, a3, a4);
            }

            mCur = mN; pCur = pN;
        }

        // warp reduce + per-warp atomics
        #pragma unroll
        for (int d = 16; d > 0; d >>= 1) {
            a0 += __shfl_down_sync(0xffffffffu, a0, d);
            a1 += __shfl_down_sync(0xffffffffu, a1, d);
            a2 += __shfl_down_sync(0xffffffffu, a2, d);
            a3 += __shfl_down_sync(0xffffffffu, a3, d);
            a4 += __shfl_down_sync(0xffffffffu, a4, d);
        }
        if (lane == 0) {
            atomicAdd(&g_accum[b * 5 + 0], a0);
            atomicAdd(&g_accum[b * 5 + 1], a1);
            atomicAdd(&g_accum[b * 5 + 2], a2);
            atomicAdd(&g_accum[b * 5 + 3], a3);
            atomicAdd(&g_accum[b * 5 + 4], a4);
        }
    }

    // ---- last-block finalize ----
    __threadfence();
    __syncthreads();
    if (tid == 0) {
        unsigned int cdone = atomicAdd(&g_count, 1u);
        *sflag = (cdone == (unsigned int)(gridDim.x - 1)) ? 1u : 0u;
    }
    __syncthreads();
    if (*sflag && tid == 0) {
        float vals[BATCH * 5];
        #pragma unroll 1
        for (int i = 0; i < BATCH * 5; ++i) vals[i] = atomicAdd(&g_accum[i], 0.f);
        float mae_total = 0.f;
        for (int bb = 0; bb < BATCH; ++bb) mae_total += vals[bb * 5 + 4];
        const float mae = mae_total / (float)((long long)BATCH * HW);
        float acc = 0.f;
        for (int bb = 0; bb < BATCH; ++bb) {
            float ws = vals[bb * 5 + 0];
            float wb = vals[bb * 5 + 1];
            float it = vals[bb * 5 + 2];
            float un = vals[bb * 5 + 3];
            float wbce = wb / ws;
            float wiou = 1.f - (it + 1.f) / (un - it + 1.f);
            float wmae = mae * ws / (ws - (float)HW);
            acc += 0.7f * (wbce + wiou + wmae);
        }
        out[0] = acc / (float)BATCH;
        #pragma unroll 1
        for (int i = 0; i < BATCH * 5; ++i) g_accum[i] = 0.f;
        __threadfence();
        atomicExch(&g_count, 0u);
    }
}

extern "C" void kernel_launch(void* const* d_in, const int* in_sizes, int n_in,
                              void* d_out, int out_size) {
    const float* pred = (const float*)d_in[0];
    const float* mask = (const float*)d_in[1];
    float* out = (float*)d_out;

    const int smem_bytes = WPB * WARPF4 * 16 + 16;
    cudaFuncSetAttribute(adaptive_loss_main,
                         cudaFuncAttributeMaxDynamicSharedMemorySize, smem_bytes);
    adaptive_loss_main<<<NCTA, NT, smem_bytes>>>(pred, mask, out);
}

// round 13
// speedup vs baseline: 1.4870x; 1.0010x over previous
#include <cuda_runtime.h>

#define BATCH  16
#define H      1024
#define HW     (H*H)
#define NSTRIP 11
#define NBANDS 10
#define BANDH  103
#define TASKS  (BATCH*NSTRIP*NBANDS)   // 1760
#define WPB    12
#define NT     384
#define NCTA   ((TASKS+WPB-1)/WPB)     // 147
#define WARPF4 1024                    // ring only: 32 slots x 32 f4 = 16 KB/warp

__device__ float        g_accum[BATCH * 5];
__device__ unsigned int g_count;

__device__ __forceinline__ float4 f4z() { return make_float4(0.f, 0.f, 0.f, 0.f); }
__device__ __forceinline__ void addf4(float4& a, const float4 b) { a.x+=b.x; a.y+=b.y; a.z+=b.z; a.w+=b.w; }

__device__ __forceinline__ void epi(float x, float m, float S3, float S15, float S31,
                                    float& a0, float& a1, float& a2, float& a3, float& a4)
{
    float w = 1.f + 5.f * ( fabsf(S3  * (1.f / 9.f)   - m)
                          + fabsf(S15 * (1.f / 225.f) - m)
                          + fabsf(S31 * (1.f / 961.f) - m) );
    float e   = __expf(-fabsf(x));
    float l   = __logf(1.f + e);
    float bce = fmaxf(x, 0.f) - x * m + l;
    float inv = __fdividef(1.f, 1.f + e);
    float sg  = (x >= 0.f) ? inv : e * inv;
    a0 += w;
    a1 += w * bce;
    a2 += sg * m * w;
    a3 += (sg + m) * w;
    a4 += fabsf(sg - m);
}

__global__ __launch_bounds__(NT, 1) void adaptive_loss_main(
    const float* __restrict__ pred, const float* __restrict__ mask, float* __restrict__ out)
{
    extern __shared__ float4 sm4[];
    unsigned int* sflag = (unsigned int*)(sm4 + WPB * WARPF4);
    const int tid  = threadIdx.x;
    const int lane = tid & 31;
    const int warp = tid >> 5;
    const int task = blockIdx.x * WPB + warp;

    float a0 = 0.f, a1 = 0.f, a2 = 0.f, a3 = 0.f, a4 = 0.f;
    int b = 0;

    if (task < TASKS) {
        b = task / (NSTRIP * NBANDS);
        const int rem  = task % (NSTRIP * NBANDS);
        const int s    = rem / NBANDS;
        const int band = rem % NBANDS;
        const int y0   = band * BANDH;
        const int rows = (H - y0 < BANDH) ? (H - y0) : BANDH;

        const float4* mb4 = (const float4*)(mask + (size_t)b * HW);
        const float4* pb4 = (const float4*)(pred + (size_t)b * HW);

        const int  w     = 24 * s - 4 + lane;     // global f4 word
        const bool ok    = ((unsigned)w < 256u);
        const bool dataT = (lane >= 4) && (lane <= 27) && ((24 * s + lane - 4) < 256);

        float4* rg = sm4 + warp * WARPF4;         // per-warp, per-lane ring: slot*32 + lane

        float4 U31 = f4z(), U15 = f4z(), U3 = f4z();

        // ---------- priming: rows y0-16 .. y0+14 ----------
        float4 mCur;
        {
            int r = y0 - 16;
            mCur = (r >= 0 && ok) ? mb4[(size_t)r * 256 + w] : f4z();
        }
        float4 mP = f4z(), mPm1 = f4z(), mPm2 = f4z();
        #pragma unroll 1
        for (int j = 0; j < 31; ++j) {
            const int r = y0 - 16 + j, rn = r + 1;
            float4 mN = (rn >= 0 && rn < H && ok) ? mb4[(size_t)rn * 256 + w] : f4z();

            float4 v = mCur; v.y += v.x; v.z += v.y; v.w += v.z;
            float tot = v.w;
            #pragma unroll
            for (int d = 1; d < 32; d <<= 1) {
                float u = __shfl_up_sync(0xffffffffu, tot, d);
                if (lane >= d) tot += u;
            }
            const float ex = tot - v.w;
            float4 P = make_float4(v.x + ex, v.y + ex, v.z + ex, v.w + ex);
            rg[((r + 512) & 31) * 32 + lane] = P;

            addf4(U31, P);
            if (j >= 8  && j <= 22) addf4(U15, P);
            if (j >= 14 && j <= 16) addf4(U3,  P);
            if (j == 14) mPm2 = P;                 // P(y0-2)
            if (j == 15) mPm1 = P;                 // P(y0-1)
            if (j == 16) mP   = P;                 // P(y0)

            mCur = mN;
        }
        // mCur = raw mask row y0+15; U centered at y0-1

        float4 pCur = dataT ? pb4[(size_t)y0 * 256 + w] : f4z();

        // ---------- main ----------
        #pragma unroll 1
        for (int i = 0; i < rows; ++i) {
            const int y  = y0 + i;
            const int rn = y + 16;
            float4 mN = (rn < H && ok) ? mb4[(size_t)rn * 256 + w] : f4z();
            float4 pN = (dataT && (y + 1 < H)) ? pb4[(size_t)(y + 1) * 256 + w] : f4z();

            // warp-local scan of mask row y+15
            float4 v = mCur; v.y += v.x; v.z += v.y; v.w += v.z;
            float tot = v.w;
            #pragma unroll
            for (int d = 1; d < 32; d <<= 1) {
                float u = __shfl_up_sync(0xffffffffu, tot, d);
                if (lane >= d) tot += u;
            }
            const float ex = tot - v.w;
            float4 P = make_float4(v.x + ex, v.y + ex, v.z + ex, v.w + ex);
            rg[((y + 15) & 31) * 32 + lane] = P;

            // own-lane ring taps (the ONLY smem reads)
            float4 t16 = rg[((y - 16 + 512) & 31) * 32 + lane];
            float4 t7  = rg[((y + 7)        & 31) * 32 + lane];
            float4 t8  = rg[((y - 8 + 512)  & 31) * 32 + lane];
            float4 t1  = rg[((y + 1)        & 31) * 32 + lane];

            U31.x += P.x - t16.x; U31.y += P.y - t16.y; U31.z += P.z - t16.z; U31.w += P.w - t16.w;
            U15.x += t7.x - t8.x; U15.y += t7.y - t8.y; U15.z += t7.z - t8.z; U15.w += t7.w - t8.w;
            U3.x  += t1.x - mPm2.x; U3.y += t1.y - mPm2.y; U3.z += t1.z - mPm2.z; U3.w += t1.w - mPm2.w;

            // cross-lane values via register shuffles (uniform execution)
            float a31w = __shfl_down_sync(0xffffffffu, U31.w, 3);
            float b31x = __shfl_down_sync(0xffffffffu, U31.x, 4);
            float b31y = __shfl_down_sync(0xffffffffu, U31.y, 4);
            float b31z = __shfl_down_sync(0xffffffffu, U31.z, 4);
            float c31x = __shfl_up_sync(0xffffffffu, U31.x, 4);
            float c31y = __shfl_up_sync(0xffffffffu, U31.y, 4);
            float c31z = __shfl_up_sync(0xffffffffu, U31.z, 4);
            float c31w = __shfl_up_sync(0xffffffffu, U31.w, 4);
            float a15w = __shfl_down_sync(0xffffffffu, U15.w, 1);
            float b15x = __shfl_down_sync(0xffffffffu, U15.x, 2);
            float b15y = __shfl_down_sync(0xffffffffu, U15.y, 2);
            float b15z = __shfl_down_sync(0xffffffffu, U15.z, 2);
            float c15x = __shfl_up_sync(0xffffffffu, U15.x, 2);
            float c15y = __shfl_up_sync(0xffffffffu, U15.y, 2);
            float c15z = __shfl_up_sync(0xffffffffu, U15.z, 2);
            float c15w = __shfl_up_sync(0xffffffffu, U15.w, 2);
            float uz = __shfl_up_sync(0xffffffffu, U3.z, 1);      // U3(4L-2)
            float uw = __shfl_up_sync(0xffffffffu, U3.w, 1);      // U3(4L-1)
            float dx = __shfl_down_sync(0xffffffffu, U3.x, 1);    // U3(4L+4)
            float mlw = __shfl_up_sync(0xffffffffu, mP.w, 1);     // P(y)[4L-1]

            if (dataT) {
                float m0 = mP.x - mlw,  m1 = mP.y - mP.x;
                float m2 = mP.z - mP.y, m3 = mP.w - mP.z;

                epi(pCur.x, m0, U3.y - uz,   a15w - c15x, a31w - c31x, a0, a1, a2, a3, a4);
                epi(pCur.y, m1, U3.z - uw,   b15x - c15y, b31x - c31y, a0, a1, a2, a3, a4);
                epi(pCur.z, m2, U3.w - U3.x, b15y - c15z, b31y - c31z, a0, a1, a2, a3, a4);
                epi(pCur.w, m3, dx - U3.y,   b15z - c15w, b31z - c31w, a0, a1, a2, a3, a4);
            }

            mPm2 = mPm1; mPm1 = mP; mP = t1;       // rotate P(y-2),P(y-1),P(y) pipeline
            mCur = mN; pCur = pN;
        }

        // warp reduce + per-warp atomics
        #pragma unroll
        for (int d = 16; d > 0; d >>= 1) {
            a0 += __shfl_down_sync(0xffffffffu, a0, d);
            a1 += __shfl_down_sync(0xffffffffu, a1, d);
            a2 += __shfl_down_sync(0xffffffffu, a2, d);
            a3 += __shfl_down_sync(0xffffffffu, a3, d);
            a4 += __shfl_down_sync(0xffffffffu, a4, d);
        }
        if (lane == 0) {
            atomicAdd(&g_accum[b * 5 + 0], a0);
            atomicAdd(&g_accum[b * 5 + 1], a1);
            atomicAdd(&g_accum[b * 5 + 2], a2);
            atomicAdd(&g_accum[b * 5 + 3], a3);
            atomicAdd(&g_accum[b * 5 + 4], a4);
        }
    }

    // ---- last-block finalize ----
    __threadfence();
    __syncthreads();
    if (tid == 0) {
        unsigned int cdone = atomicAdd(&g_count, 1u);
        *sflag = (cdone == (unsigned int)(gridDim.x - 1)) ? 1u : 0u;
    }
    __syncthreads();
    if (*sflag && tid == 0) {
        float vals[BATCH * 5];
        #pragma unroll 1
        for (int i = 0; i < BATCH * 5; ++i) vals[i] = atomicAdd(&g_accum[i], 0.f);
        float mae_total = 0.f;
        for (int bb = 0; bb < BATCH; ++bb) mae_total += vals[bb * 5 + 4];
        const float mae = mae_total / (float)((long long)BATCH * HW);
        float acc = 0.f;
        for (int bb = 0; bb < BATCH; ++bb) {
            float ws = vals[bb * 5 + 0];
            float wb = vals[bb * 5 + 1];
            float it = vals[bb * 5 + 2];
            float un = vals[bb * 5 + 3];
            float wbce = wb / ws;
            float wiou = 1.f - (it + 1.f) / (un - it + 1.f);
            float wmae = mae * ws / (ws - (float)HW);
            acc += 0.7f * (wbce + wiou + wmae);
        }
        out[0] = acc / (float)BATCH;
        #pragma unroll 1
        for (int i = 0; i < BATCH * 5; ++i) g_accum[i] = 0.f;
        __threadfence();
        atomicExch(&g_count, 0u);
    }
}

extern "C" void kernel_launch(void* const* d_in, const int* in_sizes, int n_in,
                              void* d_out, int out_size) {
    const float* pred = (const float*)d_in[0];
    const float* mask = (const float*)d_in[1];
    float* out = (float*)d_out;

    const int smem_bytes = WPB * WARPF4 * 16 + 16;
    cudaFuncSetAttribute(adaptive_loss_main,
                         cudaFuncAttributeMaxDynamicSharedMemorySize, smem_bytes);
    adaptive_loss_main<<<NCTA, NT, smem_bytes>>>(pred, mask, out);
}